// round 7
// baseline (speedup 1.0000x reference)
#include <cuda_runtime.h>
#include <math.h>

// ---------------------------------------------------------------------------
// Problem constants
//   x  : (2, 5760, 512)  -> rows M = 11520, K = 512
//   W1 : (1960, 512), b1 : (1960)
//   W2 : (512, 1960), b2 : (512)
//   out_h=60, out_w=108, kernel 7x7, stride 3, pad 3
//   oh=20, ow=36, L=720, B'=16, C=40 (1960/49), padded image 66x114
//   fold crops to 60x108; unfold re-pads with ZEROS (ring reads are zero!)
// ---------------------------------------------------------------------------
#define DIMD   512
#define HID    1960
#define NROWS  11520
#define BPRIME 16
#define LVEC   720
#define OHh    20
#define OWw    36
#define HP     66
#define WP     114
#define NPIX   (HP * WP)   // 7524
#define NCH    40
#define PAD    3
#define OUTH   60
#define OUTW   108

// Scratch (allocation-free rule: __device__ globals)
__device__ float g_h   [(size_t)NROWS * HID];          // GEMM1 output
__device__ float g_fold[(size_t)BPRIME * NCH * NPIX];  // folded image (padded coords)
__device__ float g_act [(size_t)NROWS * HID];          // gelu(unfold(...)) = GEMM2 input

// ---------------------------------------------------------------------------
// Classic 128x128x8 fp32 SGEMM, NT layout (A: MxK row-major, B: NxK row-major)
// C[m,n] = sum_k A[m,k]*B[n,k] + bias[n].  M % 128 == 0, K % 8 == 0 assumed;
// N guarded.
// ---------------------------------------------------------------------------
__global__ __launch_bounds__(256) void sgemm_nt_bias(
    int M, int N, int K,
    const float* __restrict__ A,
    const float* __restrict__ B,
    const float* __restrict__ bias,
    float* __restrict__ C)
{
    __shared__ float As[8][128];
    __shared__ float Bs[8][128];

    const int tid = threadIdx.x;
    const int bm = blockIdx.y * 128;
    const int bn = blockIdx.x * 128;

    // Tile loader mapping: 256 threads, each loads one float4 of A and one of B.
    const int lr = tid >> 1;          // 0..127 : row within tile
    const int lc = (tid & 1) << 2;    // 0 or 4 : k-offset within BK=8

    // 8x8 microtile coordinates
    const int tx = (tid & 15) << 3;   // col in [0,128)
    const int ty = (tid >> 4) << 3;   // row in [0,128)

    float acc[8][8];
    #pragma unroll
    for (int i = 0; i < 8; i++)
        #pragma unroll
        for (int j = 0; j < 8; j++) acc[i][j] = 0.f;

    const bool bvalid = (bn + lr) < N;
    const float* Ap = A + (size_t)(bm + lr) * K + lc;
    const float* Bp = B + (size_t)(bvalid ? (bn + lr) : 0) * K + lc;

    for (int k0 = 0; k0 < K; k0 += 8) {
        float4 a4 = *(const float4*)(Ap + k0);
        float4 b4 = bvalid ? *(const float4*)(Bp + k0)
                           : make_float4(0.f, 0.f, 0.f, 0.f);
        As[lc + 0][lr] = a4.x; As[lc + 1][lr] = a4.y;
        As[lc + 2][lr] = a4.z; As[lc + 3][lr] = a4.w;
        Bs[lc + 0][lr] = b4.x; Bs[lc + 1][lr] = b4.y;
        Bs[lc + 2][lr] = b4.z; Bs[lc + 3][lr] = b4.w;
        __syncthreads();

        #pragma unroll
        for (int kk = 0; kk < 8; kk++) {
            float ar[8], br[8];
            #pragma unroll
            for (int i = 0; i < 8; i++) ar[i] = As[kk][ty + i];
            #pragma unroll
            for (int j = 0; j < 8; j++) br[j] = Bs[kk][tx + j];
            #pragma unroll
            for (int i = 0; i < 8; i++)
                #pragma unroll
                for (int j = 0; j < 8; j++)
                    acc[i][j] = fmaf(ar[i], br[j], acc[i][j]);
        }
        __syncthreads();
    }

    #pragma unroll
    for (int i = 0; i < 8; i++) {
        const int row = bm + ty + i;
        #pragma unroll
        for (int j = 0; j < 8; j++) {
            const int col = bn + tx + j;
            if (col < N)
                C[(size_t)row * N + col] = acc[i][j] + bias[col];
        }
    }
}

// ---------------------------------------------------------------------------
// Fold: gather formulation. Each padded pixel (b', c, py, px) sums its <=9
// contributing patch entries of h:  py = 3*oy + ky  with  ky in [0,7),
// 0 <= oy < 20, same for x-axis. Exactly overwrites every element.
// (Ring pixels are computed but never read downstream.)
// ---------------------------------------------------------------------------
__global__ void fold_kernel(const float* __restrict__ h, float* __restrict__ f)
{
    const int total = BPRIME * NCH * NPIX;
    int idx = blockIdx.x * blockDim.x + threadIdx.x;
    if (idx >= total) return;

    const int p = idx % NPIX;
    const int c = (idx / NPIX) % NCH;
    const int b = idx / (NPIX * NCH);
    const int py = p / WP;
    const int px = p % WP;

    float s = 0.f;
    for (int ky = py % 3; ky < 7 && ky <= py; ky += 3) {   // oy >= 0
        const int oy = (py - ky) / 3;
        if (oy >= OHh) continue;
        for (int kx = px % 3; kx < 7 && kx <= px; kx += 3) { // ox >= 0
            const int ox = (px - kx) / 3;
            if (ox >= OWw) continue;
            s += h[(size_t)(b * LVEC + oy * OWw + ox) * HID + c * 49 + ky * 7 + kx];
        }
    }
    f[idx] = s;
}

// Number of valid (k, o) pairs covering padded coordinate p along one axis.
__device__ __forceinline__ int axis_cnt(int p, int osz)
{
    int cnt = 0;
    for (int k = p % 3; k < 7 && k <= p; k += 3) {  // o >= 0
        const int o = (p - k) / 3;
        if (o < osz) cnt++;
    }
    return cnt;
}

// ---------------------------------------------------------------------------
// Unfold + norm + exact GELU fused. Writes GEMM2's A operand.
// CRITICAL: fold's output is cropped to [PAD, PAD+60) x [PAD, PAD+108) and
// unfold re-pads with zeros -> ring coordinates read 0, not folded/norm.
// ---------------------------------------------------------------------------
__global__ void unfold_gelu_kernel(const float* __restrict__ f,
                                   float* __restrict__ g)
{
    const int total = NROWS * HID;  // 22,579,200 < 2^31
    int idx = blockIdx.x * blockDim.x + threadIdx.x;
    if (idx >= total) return;

    const int col = idx % HID;
    const int m   = idx / HID;
    const int c  = col / 49;
    const int k  = col % 49;
    const int b  = m / LVEC;
    const int l  = m % LVEC;
    const int oy = l / OWw;
    const int ox = l % OWw;
    const int ky = k / 7;
    const int kx = k % 7;
    const int py = 3 * oy + ky;
    const int px = 3 * ox + kx;

    float r = 0.f;
    // inside the cropped (un-padded) region?
    if (py >= PAD && py < PAD + OUTH && px >= PAD && px < PAD + OUTW) {
        const float norm = (float)(axis_cnt(py, OHh) * axis_cnt(px, OWw));
        const float v = f[((size_t)(b * NCH + c)) * NPIX + py * WP + px] / norm;
        // exact gelu: 0.5 * v * (1 + erf(v / sqrt(2)))
        r = 0.5f * v * (1.f + erff(v * 0.70710678118654752f));
    }
    g[idx] = r;
}

// ---------------------------------------------------------------------------
// Launch
// ---------------------------------------------------------------------------
extern "C" void kernel_launch(void* const* d_in, const int* in_sizes, int n_in,
                              void* d_out, int out_size)
{
    const float* x  = (const float*)d_in[0];  // (11520, 512)
    const float* W1 = (const float*)d_in[1];  // (1960, 512)
    const float* b1 = (const float*)d_in[2];  // (1960)
    const float* W2 = (const float*)d_in[3];  // (512, 1960)
    const float* b2 = (const float*)d_in[4];  // (512)
    float* out = (float*)d_out;               // (11520, 512)

    float *hptr, *fptr, *gptr;
    cudaGetSymbolAddress((void**)&hptr, g_h);
    cudaGetSymbolAddress((void**)&fptr, g_fold);
    cudaGetSymbolAddress((void**)&gptr, g_act);

    // GEMM1: h = x @ W1^T + b1   (M=11520, N=1960, K=512)
    {
        dim3 grid((HID + 127) / 128, NROWS / 128);
        sgemm_nt_bias<<<grid, 256>>>(NROWS, HID, DIMD, x, W1, b1, hptr);
    }

    // Fold (gather)
    {
        const int total = BPRIME * NCH * NPIX;
        fold_kernel<<<(total + 255) / 256, 256>>>(hptr, fptr);
    }

    // Unfold + norm + gelu (with crop-to-zero ring semantics)
    {
        const int total = NROWS * HID;
        unfold_gelu_kernel<<<(total + 255) / 256, 256>>>(fptr, gptr);
    }

    // GEMM2: out = g @ W2^T + b2  (M=11520, N=512, K=1960)
    {
        dim3 grid((DIMD + 127) / 128, NROWS / 128);
        sgemm_nt_bias<<<grid, 256>>>(NROWS, DIMD, HID, gptr, W2, b2, out);
    }
}

// round 8
// speedup vs baseline: 1.5370x; 1.5370x over previous
#include <cuda_runtime.h>
#include <cuda_bf16.h>
#include <mma.h>
#include <math.h>

using namespace nvcuda;

// ---------------------------------------------------------------------------
// Problem constants
//   x  : (2, 5760, 512)  -> rows M = 11520, K = 512
//   W1 : (1960, 512), b1 : (1960)
//   W2 : (512, 1960), b2 : (512)
//   out_h=60, out_w=108, kernel 7x7, stride 3, pad 3
//   oh=20, ow=36, L=720, B'=16, C=40 (1960/49), padded image 66x114
//   fold crops to 60x108; unfold re-pads with ZEROS (ring reads are zero!)
// ---------------------------------------------------------------------------
#define DIMD   512
#define HID    1960
#define NROWS  11520
#define BPRIME 16
#define LVEC   720
#define OHh    20
#define OWw    36
#define HP     66
#define WP     114
#define NPIX   (HP * WP)   // 7524
#define NCH    40
#define PAD    3
#define OUTH   60
#define OUTW   108

// GEMM tiling
#define BM 128
#define BN 128
#define BK 32
#define LDT 48            // smem leading dim in bf16 elements (96B, 16B-aligned)
#define GEMM_SMEM 65536   // max(mainloop 49152, epilogue staging 65536)

// Scratch (allocation-free rule: __device__ globals)
__device__ float g_h   [(size_t)NROWS * HID];          // GEMM1 output
__device__ float g_fold[(size_t)BPRIME * NCH * NPIX];  // folded image (padded coords)
__device__ float g_act [(size_t)NROWS * HID];          // gelu(unfold(...)) = GEMM2 input

// ---------------------------------------------------------------------------
// bf16x3 split-precision tensor-core GEMM, NT layout.
//   C[m,n] = sum_k A[m,k]*B[n,k] + bias[n]
// A: MxK row-major fp32, B: NxK row-major fp32 (converted to bf16 hi/lo on
// the fly). Accumulate Ah*Bh + Al*Bh + Ah*Bl in fp32 accumulators.
// M % 128 == 0 assumed; N, K ragged (guarded, zero-filled).
// Block 128x128x32, 8 warps (2x4), warp tile 64x32 (4x2 wmma 16x16 frags).
// ---------------------------------------------------------------------------
__global__ __launch_bounds__(256) void gemm_bf16x3_nt_bias(
    int M, int N, int K,
    const float* __restrict__ A,
    const float* __restrict__ B,
    const float* __restrict__ bias,
    float* __restrict__ C)
{
    extern __shared__ char smem_raw[];
    __nv_bfloat16* As_hi = (__nv_bfloat16*)smem_raw;          // [BM][LDT]
    __nv_bfloat16* As_lo = As_hi + BM * LDT;
    __nv_bfloat16* Bs_hi = As_lo + BM * LDT;                  // [BN][LDT]
    __nv_bfloat16* Bs_lo = Bs_hi + BN * LDT;
    float* stage = (float*)smem_raw;                          // epilogue reuse

    const int tid    = threadIdx.x;
    const int warpid = tid >> 5;
    const int lane   = tid & 31;
    const int wm     = warpid >> 2;   // 0..1 : 64-row slab
    const int wn     = warpid & 3;    // 0..3 : 32-col slab
    const int bm     = blockIdx.y * BM;
    const int bn     = blockIdx.x * BN;

    wmma::fragment<wmma::accumulator, 16, 16, 16, float> acc[4][2];
    #pragma unroll
    for (int i = 0; i < 4; i++)
        #pragma unroll
        for (int j = 0; j < 2; j++)
            wmma::fill_fragment(acc[i][j], 0.f);

    // loader mapping: 8 threads per row (4 consecutive k each), 32 rows/pass
    const int lrow = tid >> 3;          // 0..31
    const int lcb  = (tid & 7) * 4;     // 0,4,...,28

    for (int k0 = 0; k0 < K; k0 += BK) {
        #pragma unroll
        for (int p = 0; p < 4; p++) {
            const int r = lrow + p * 32;          // tile row 0..127
            #pragma unroll
            for (int q = 0; q < 4; q++) {
                const int kc = lcb + q;           // 0..31
                const int k  = k0 + kc;
                const bool kok = (k < K);
                // A tile (M guaranteed in range: M % 128 == 0)
                float va = kok ? A[(size_t)(bm + r) * K + k] : 0.f;
                __nv_bfloat16 ah = __float2bfloat16(va);
                As_hi[r * LDT + kc] = ah;
                As_lo[r * LDT + kc] = __float2bfloat16(va - __bfloat162float(ah));
                // B tile (guard n)
                const int n = bn + r;
                float vb = (kok && n < N) ? B[(size_t)n * K + k] : 0.f;
                __nv_bfloat16 bh = __float2bfloat16(vb);
                Bs_hi[r * LDT + kc] = bh;
                Bs_lo[r * LDT + kc] = __float2bfloat16(vb - __bfloat162float(bh));
            }
        }
        __syncthreads();

        #pragma unroll
        for (int kk = 0; kk < BK; kk += 16) {
            wmma::fragment<wmma::matrix_a, 16, 16, 16, __nv_bfloat16, wmma::row_major> a_hi[4], a_lo[4];
            wmma::fragment<wmma::matrix_b, 16, 16, 16, __nv_bfloat16, wmma::col_major> b_hi[2], b_lo[2];
            #pragma unroll
            for (int i = 0; i < 4; i++) {
                const int row = wm * 64 + i * 16;
                wmma::load_matrix_sync(a_hi[i], As_hi + row * LDT + kk, LDT);
                wmma::load_matrix_sync(a_lo[i], As_lo + row * LDT + kk, LDT);
            }
            #pragma unroll
            for (int j = 0; j < 2; j++) {
                const int col = wn * 32 + j * 16;
                // B^T is (K x N) col-major: element (k, n) at Bs[n*LDT + k]
                wmma::load_matrix_sync(b_hi[j], Bs_hi + col * LDT + kk, LDT);
                wmma::load_matrix_sync(b_lo[j], Bs_lo + col * LDT + kk, LDT);
            }
            #pragma unroll
            for (int i = 0; i < 4; i++)
                #pragma unroll
                for (int j = 0; j < 2; j++) {
                    wmma::mma_sync(acc[i][j], a_hi[i], b_hi[j], acc[i][j]);
                    wmma::mma_sync(acc[i][j], a_lo[i], b_hi[j], acc[i][j]);
                    wmma::mma_sync(acc[i][j], a_hi[i], b_lo[j], acc[i][j]);
                }
        }
        __syncthreads();   // also guards epilogue smem reuse after last iter
    }

    // Epilogue: stage each warp's 64x32 fp32 tile in smem, then guarded
    // global writes with bias (N may not be a multiple of 16).
    float* wstage = stage + warpid * (64 * 32);
    #pragma unroll
    for (int i = 0; i < 4; i++)
        #pragma unroll
        for (int j = 0; j < 2; j++)
            wmma::store_matrix_sync(wstage + i * 16 * 32 + j * 16, acc[i][j],
                                    32, wmma::mem_row_major);
    __syncwarp();

    const int grow0 = bm + wm * 64;
    const int gcol0 = bn + wn * 32;
    for (int e = lane; e < 64 * 32; e += 32) {
        const int r = e >> 5;
        const int c = e & 31;
        const int gc = gcol0 + c;
        if (gc < N)
            C[(size_t)(grow0 + r) * N + gc] = wstage[e] + bias[gc];
    }
}

// ---------------------------------------------------------------------------
// Fold: gather formulation. Each padded pixel (b', c, py, px) sums its <=9
// contributing patch entries of h:  py = 3*oy + ky,  0 <= oy < 20, etc.
// Exactly overwrites every element. (Ring pixels computed, never read.)
// ---------------------------------------------------------------------------
__global__ void fold_kernel(const float* __restrict__ h, float* __restrict__ f)
{
    const int total = BPRIME * NCH * NPIX;
    int idx = blockIdx.x * blockDim.x + threadIdx.x;
    if (idx >= total) return;

    const int p = idx % NPIX;
    const int c = (idx / NPIX) % NCH;
    const int b = idx / (NPIX * NCH);
    const int py = p / WP;
    const int px = p % WP;

    float s = 0.f;
    for (int ky = py % 3; ky < 7 && ky <= py; ky += 3) {   // oy >= 0
        const int oy = (py - ky) / 3;
        if (oy >= OHh) continue;
        for (int kx = px % 3; kx < 7 && kx <= px; kx += 3) { // ox >= 0
            const int ox = (px - kx) / 3;
            if (ox >= OWw) continue;
            s += h[(size_t)(b * LVEC + oy * OWw + ox) * HID + c * 49 + ky * 7 + kx];
        }
    }
    f[idx] = s;
}

// Number of valid (k, o) pairs covering padded coordinate p along one axis.
__device__ __forceinline__ int axis_cnt(int p, int osz)
{
    int cnt = 0;
    for (int k = p % 3; k < 7 && k <= p; k += 3) {  // o >= 0
        const int o = (p - k) / 3;
        if (o < osz) cnt++;
    }
    return cnt;
}

// ---------------------------------------------------------------------------
// Unfold + norm + exact GELU fused. Writes GEMM2's A operand.
// fold's output is cropped to [PAD, PAD+60) x [PAD, PAD+108) and unfold
// re-pads with zeros -> ring coordinates read 0.
// ---------------------------------------------------------------------------
__global__ void unfold_gelu_kernel(const float* __restrict__ f,
                                   float* __restrict__ g)
{
    const int total = NROWS * HID;  // 22,579,200 < 2^31
    int idx = blockIdx.x * blockDim.x + threadIdx.x;
    if (idx >= total) return;

    const int col = idx % HID;
    const int m   = idx / HID;
    const int c  = col / 49;
    const int k  = col % 49;
    const int b  = m / LVEC;
    const int l  = m % LVEC;
    const int oy = l / OWw;
    const int ox = l % OWw;
    const int ky = k / 7;
    const int kx = k % 7;
    const int py = 3 * oy + ky;
    const int px = 3 * ox + kx;

    float r = 0.f;
    if (py >= PAD && py < PAD + OUTH && px >= PAD && px < PAD + OUTW) {
        const float norm = (float)(axis_cnt(py, OHh) * axis_cnt(px, OWw));
        const float v = f[((size_t)(b * NCH + c)) * NPIX + py * WP + px] / norm;
        // exact gelu: 0.5 * v * (1 + erf(v / sqrt(2)))
        r = 0.5f * v * (1.f + erff(v * 0.70710678118654752f));
    }
    g[idx] = r;
}

// ---------------------------------------------------------------------------
// Launch
// ---------------------------------------------------------------------------
extern "C" void kernel_launch(void* const* d_in, const int* in_sizes, int n_in,
                              void* d_out, int out_size)
{
    const float* x  = (const float*)d_in[0];  // (11520, 512)
    const float* W1 = (const float*)d_in[1];  // (1960, 512)
    const float* b1 = (const float*)d_in[2];  // (1960)
    const float* W2 = (const float*)d_in[3];  // (512, 1960)
    const float* b2 = (const float*)d_in[4];  // (512)
    float* out = (float*)d_out;               // (11520, 512)

    float *hptr, *fptr, *gptr;
    cudaGetSymbolAddress((void**)&hptr, g_h);
    cudaGetSymbolAddress((void**)&fptr, g_fold);
    cudaGetSymbolAddress((void**)&gptr, g_act);

    static bool attr_set = false;
    if (!attr_set) {
        cudaFuncSetAttribute(gemm_bf16x3_nt_bias,
                             cudaFuncAttributeMaxDynamicSharedMemorySize,
                             GEMM_SMEM);
        attr_set = true;
    }

    // GEMM1: h = x @ W1^T + b1   (M=11520, N=1960, K=512)
    {
        dim3 grid((HID + BN - 1) / BN, NROWS / BM);
        gemm_bf16x3_nt_bias<<<grid, 256, GEMM_SMEM>>>(
            NROWS, HID, DIMD, x, W1, b1, hptr);
    }

    // Fold (gather)
    {
        const int total = BPRIME * NCH * NPIX;
        fold_kernel<<<(total + 255) / 256, 256>>>(hptr, fptr);
    }

    // Unfold + norm + gelu (with crop-to-zero ring semantics)
    {
        const int total = NROWS * HID;
        unfold_gelu_kernel<<<(total + 255) / 256, 256>>>(fptr, gptr);
    }

    // GEMM2: out = g @ W2^T + b2  (M=11520, N=512, K=1960)
    {
        dim3 grid((DIMD + BN - 1) / BN, NROWS / BM);
        gemm_bf16x3_nt_bias<<<grid, 256, GEMM_SMEM>>>(
            NROWS, DIMD, HID, gptr, W2, b2, out);
    }
}

// round 14
// speedup vs baseline: 2.4457x; 1.5912x over previous
#include <cuda_runtime.h>
#include <cuda_bf16.h>
#include <mma.h>
#include <math.h>
#include <stdint.h>

using namespace nvcuda;

// ---------------------------------------------------------------------------
// Problem constants
//   x  : (2, 5760, 512)  -> rows M = 11520, K = 512
//   W1 : (1960, 512), b1 : (1960)
//   W2 : (512, 1960), b2 : (512)
//   out_h=60, out_w=108, kernel 7x7, stride 3, pad 3
//   oh=20, ow=36, L=720, B'=16, C=40 (1960/49), padded image 66x114
//   fold crops to 60x108; unfold re-pads with ZEROS (ring reads are zero!)
// ---------------------------------------------------------------------------
#define DIMD   512
#define HID    1960
#define NROWS  11520
#define BPRIME 16
#define LVEC   720
#define OHh    20
#define OWw    36
#define HP     66
#define WP     114
#define NPIX   (HP * WP)   // 7524
#define NCH    40
#define PAD    3
#define OUTH   60
#define OUTW   108

// GEMM tiling
#define BM 128
#define BN 128
#define BK 64
#define LDT 72                         // 64 + 8 bf16 pad (16B) vs bank conflicts
#define TILE_ELEMS (128 * LDT)
#define GEMM_SMEM (2 * 4 * TILE_ELEMS * 2)   // 2 stages x 4 arrays x bf16 = 147456

// Scratch (allocation-free rule: __device__ globals)
__device__ float g_h   [(size_t)NROWS * HID];          // GEMM1 output (fp32, fold input)
__device__ float g_fold[(size_t)BPRIME * NCH * NPIX];  // folded image
__device__ __nv_bfloat16 g_xh [(size_t)NROWS * DIMD];  // x split hi/lo
__device__ __nv_bfloat16 g_xl [(size_t)NROWS * DIMD];
__device__ __nv_bfloat16 g_w1h[(size_t)HID * DIMD];
__device__ __nv_bfloat16 g_w1l[(size_t)HID * DIMD];
__device__ __nv_bfloat16 g_w2h[(size_t)DIMD * HID];
__device__ __nv_bfloat16 g_w2l[(size_t)DIMD * HID];
__device__ __nv_bfloat16 g_gh [(size_t)NROWS * HID];   // gelu(unfold) split hi/lo
__device__ __nv_bfloat16 g_gl [(size_t)NROWS * HID];

// ---------------------------------------------------------------------------
// cp.async helpers
// ---------------------------------------------------------------------------
__device__ __forceinline__ void cp_async16(void* smem_dst, const void* gmem_src,
                                           bool pred)
{
    unsigned int saddr = (unsigned int)__cvta_generic_to_shared(smem_dst);
    int src_bytes = pred ? 16 : 0;    // 0 -> zero-fill, no read
    asm volatile("cp.async.cg.shared.global [%0], [%1], 16, %2;\n"
                 :: "r"(saddr), "l"(gmem_src), "r"(src_bytes));
}
__device__ __forceinline__ void cp_async_commit()
{
    asm volatile("cp.async.commit_group;\n" ::: "memory");
}
template <int N>
__device__ __forceinline__ void cp_async_wait()
{
    asm volatile("cp.async.wait_group %0;\n" :: "n"(N) : "memory");
}

// ---------------------------------------------------------------------------
// fp32 -> (bf16 hi, bf16 lo) split, vectorized.
// ---------------------------------------------------------------------------
__global__ void split_bf16_kernel(const float* __restrict__ src,
                                  __nv_bfloat16* __restrict__ hi,
                                  __nv_bfloat16* __restrict__ lo, int n4)
{
    int i = blockIdx.x * blockDim.x + threadIdx.x;
    if (i >= n4) return;
    float4 v = ((const float4*)src)[i];
    __nv_bfloat16 h0 = __float2bfloat16(v.x), h1 = __float2bfloat16(v.y);
    __nv_bfloat16 h2 = __float2bfloat16(v.z), h3 = __float2bfloat16(v.w);
    __nv_bfloat162 H0 = {h0, h1}, H1 = {h2, h3};
    __nv_bfloat162 L0 = {__float2bfloat16(v.x - __bfloat162float(h0)),
                         __float2bfloat16(v.y - __bfloat162float(h1))};
    __nv_bfloat162 L1 = {__float2bfloat16(v.z - __bfloat162float(h2)),
                         __float2bfloat16(v.w - __bfloat162float(h3))};
    ((__nv_bfloat162*)hi)[i * 2 + 0] = H0;
    ((__nv_bfloat162*)hi)[i * 2 + 1] = H1;
    ((__nv_bfloat162*)lo)[i * 2 + 0] = L0;
    ((__nv_bfloat162*)lo)[i * 2 + 1] = L1;
}

// ---------------------------------------------------------------------------
// bf16x3 split-precision tensor-core GEMM, NT layout, double-buffered cp.async.
//   C[m,n] = sum_k A[m,k]*B[n,k] + bias[n]   (fp32 accum, fp32 out)
// A,B pre-split into bf16 hi/lo arrays (row-major, K contiguous).
// M % 128 == 0 assumed. N ragged (zfill + guarded epilogue). K % 8 == 0.
// Block 128x128x64, 8 warps (2x4), warp tile 64x32 (4x2 wmma 16x16 frags).
// ---------------------------------------------------------------------------
__global__ __launch_bounds__(256) void gemm_bf16x3_nt_bias(
    int M, int N, int K,
    const __nv_bfloat16* __restrict__ Ah, const __nv_bfloat16* __restrict__ Al,
    const __nv_bfloat16* __restrict__ Bh, const __nv_bfloat16* __restrict__ Bl,
    const float* __restrict__ bias,
    float* __restrict__ C)
{
    extern __shared__ char smem_raw[];
    __nv_bfloat16* smem = (__nv_bfloat16*)smem_raw;
    // [stage][array][128][LDT]; arrays: 0=Ah 1=Al 2=Bh 3=Bl

    const int tid    = threadIdx.x;
    const int warpid = tid >> 5;
    const int lane   = tid & 31;
    const int wm     = warpid >> 2;   // 0..1 : 64-row slab
    const int wn     = warpid & 3;    // 0..3 : 32-col slab
    const int bm     = blockIdx.y * BM;
    const int bn     = blockIdx.x * BN;

    wmma::fragment<wmma::accumulator, 16, 16, 16, float> acc[4][2];
    #pragma unroll
    for (int i = 0; i < 4; i++)
        #pragma unroll
        for (int j = 0; j < 2; j++)
            wmma::fill_fragment(acc[i][j], 0.f);

    // prefetch one stage: 4 arrays x 128 rows x 8 chunks(16B) = 4096 chunks,
    // 256 threads -> 4 chunk-quads each
    auto prefetch = [&](int stage, int k0) {
        __nv_bfloat16* sb = smem + stage * 4 * TILE_ELEMS;
        #pragma unroll
        for (int i = 0; i < 4; i++) {
            const int c   = tid + 256 * i;   // 0..1023
            const int row = c >> 3;
            const int ch  = c & 7;
            const int k   = k0 + ch * 8;
            const bool kok = (k < K);        // K % 8 == 0 -> chunk-granular
            const size_t aoff = (size_t)(bm + row) * K + k;
            __nv_bfloat16* d = sb + row * LDT + ch * 8;
            cp_async16(d + 0 * TILE_ELEMS, Ah + aoff, kok);
            cp_async16(d + 1 * TILE_ELEMS, Al + aoff, kok);
            const int nrow = bn + row;
            const bool nok = kok && (nrow < N);
            const size_t boff = (size_t)(nrow < N ? nrow : N - 1) * K + k;
            cp_async16(d + 2 * TILE_ELEMS, Bh + boff, nok);
            cp_async16(d + 3 * TILE_ELEMS, Bl + boff, nok);
        }
        cp_async_commit();
    };

    const int niter = (K + BK - 1) / BK;
    prefetch(0, 0);

    for (int it = 0; it < niter; it++) {
        const int stage = it & 1;
        if (it + 1 < niter) {
            prefetch(stage ^ 1, (it + 1) * BK);
            cp_async_wait<1>();
        } else {
            cp_async_wait<0>();
        }
        __syncthreads();

        const __nv_bfloat16* sAh = smem + (stage * 4 + 0) * TILE_ELEMS;
        const __nv_bfloat16* sAl = smem + (stage * 4 + 1) * TILE_ELEMS;
        const __nv_bfloat16* sBh = smem + (stage * 4 + 2) * TILE_ELEMS;
        const __nv_bfloat16* sBl = smem + (stage * 4 + 3) * TILE_ELEMS;

        #pragma unroll
        for (int kk = 0; kk < BK; kk += 16) {
            wmma::fragment<wmma::matrix_a, 16, 16, 16, __nv_bfloat16, wmma::row_major> a_hi[4], a_lo[4];
            wmma::fragment<wmma::matrix_b, 16, 16, 16, __nv_bfloat16, wmma::col_major> b_hi[2], b_lo[2];
            #pragma unroll
            for (int i = 0; i < 4; i++) {
                const int row = wm * 64 + i * 16;
                wmma::load_matrix_sync(a_hi[i], sAh + row * LDT + kk, LDT);
                wmma::load_matrix_sync(a_lo[i], sAl + row * LDT + kk, LDT);
            }
            #pragma unroll
            for (int j = 0; j < 2; j++) {
                const int col = wn * 32 + j * 16;
                wmma::load_matrix_sync(b_hi[j], sBh + col * LDT + kk, LDT);
                wmma::load_matrix_sync(b_lo[j], sBl + col * LDT + kk, LDT);
            }
            #pragma unroll
            for (int i = 0; i < 4; i++)
                #pragma unroll
                for (int j = 0; j < 2; j++) {
                    wmma::mma_sync(acc[i][j], a_hi[i], b_hi[j], acc[i][j]);
                    wmma::mma_sync(acc[i][j], a_lo[i], b_hi[j], acc[i][j]);
                    wmma::mma_sync(acc[i][j], a_hi[i], b_lo[j], acc[i][j]);
                }
        }
        __syncthreads();
    }

    // Epilogue: stage each warp's 64x32 fp32 tile in smem (reuse pipeline
    // buffers; all compute done), then guarded global writes with bias.
    float* wstage = (float*)smem_raw + warpid * (64 * 32);
    #pragma unroll
    for (int i = 0; i < 4; i++)
        #pragma unroll
        for (int j = 0; j < 2; j++)
            wmma::store_matrix_sync(wstage + i * 16 * 32 + j * 16, acc[i][j],
                                    32, wmma::mem_row_major);
    __syncwarp();

    const int grow0 = bm + wm * 64;
    const int gcol0 = bn + wn * 32;
    for (int e = lane; e < 64 * 32; e += 32) {
        const int r = e >> 5;
        const int c = e & 31;
        const int gc = gcol0 + c;
        if (gc < N)
            C[(size_t)(grow0 + r) * N + gc] = wstage[e] + bias[gc];
    }
}

// ---------------------------------------------------------------------------
// Fold: gather formulation. Each padded pixel (b', c, py, px) sums its <=9
// contributing patch entries of h. Exactly overwrites every element.
// ---------------------------------------------------------------------------
__global__ void fold_kernel(const float* __restrict__ h, float* __restrict__ f)
{
    const int total = BPRIME * NCH * NPIX;
    int idx = blockIdx.x * blockDim.x + threadIdx.x;
    if (idx >= total) return;

    const int p = idx % NPIX;
    const int c = (idx / NPIX) % NCH;
    const int b = idx / (NPIX * NCH);
    const int py = p / WP;
    const int px = p % WP;

    float s = 0.f;
    for (int ky = py % 3; ky < 7 && ky <= py; ky += 3) {   // oy >= 0
        const int oy = (py - ky) / 3;
        if (oy >= OHh) continue;
        for (int kx = px % 3; kx < 7 && kx <= px; kx += 3) { // ox >= 0
            const int ox = (px - kx) / 3;
            if (ox >= OWw) continue;
            s += h[(size_t)(b * LVEC + oy * OWw + ox) * HID + c * 49 + ky * 7 + kx];
        }
    }
    f[idx] = s;
}

// Number of valid (k, o) pairs covering padded coordinate p along one axis.
__device__ __forceinline__ int axis_cnt(int p, int osz)
{
    int cnt = 0;
    for (int k = p % 3; k < 7 && k <= p; k += 3) {  // o >= 0
        const int o = (p - k) / 3;
        if (o < osz) cnt++;
    }
    return cnt;
}

// ---------------------------------------------------------------------------
// Unfold + norm + exact GELU fused; emits bf16 hi/lo (GEMM2 A operand).
// fold output is cropped to [PAD, PAD+60) x [PAD, PAD+108); unfold re-pads
// with zeros -> ring coordinates read 0.
// ---------------------------------------------------------------------------
__global__ void unfold_gelu_kernel(const float* __restrict__ f,
                                   __nv_bfloat16* __restrict__ gh,
                                   __nv_bfloat16* __restrict__ gl)
{
    const int total = NROWS * HID;  // 22,579,200 < 2^31
    int idx = blockIdx.x * blockDim.x + threadIdx.x;
    if (idx >= total) return;

    const int col = idx % HID;
    const int m   = idx / HID;
    const int c  = col / 49;
    const int k  = col % 49;
    const int b  = m / LVEC;
    const int l  = m % LVEC;
    const int oy = l / OWw;
    const int ox = l % OWw;
    const int ky = k / 7;
    const int kx = k % 7;
    const int py = 3 * oy + ky;
    const int px = 3 * ox + kx;

    float r = 0.f;
    if (py >= PAD && py < PAD + OUTH && px >= PAD && px < PAD + OUTW) {
        const float norm = (float)(axis_cnt(py, OHh) * axis_cnt(px, OWw));
        const float v = f[((size_t)(b * NCH + c)) * NPIX + py * WP + px] / norm;
        r = 0.5f * v * (1.f + erff(v * 0.70710678118654752f));
    }
    __nv_bfloat16 rh = __float2bfloat16(r);
    gh[idx] = rh;
    gl[idx] = __float2bfloat16(r - __bfloat162float(rh));
}

// ---------------------------------------------------------------------------
// Launch
// ---------------------------------------------------------------------------
extern "C" void kernel_launch(void* const* d_in, const int* in_sizes, int n_in,
                              void* d_out, int out_size)
{
    const float* x  = (const float*)d_in[0];  // (11520, 512)
    const float* W1 = (const float*)d_in[1];  // (1960, 512)
    const float* b1 = (const float*)d_in[2];  // (1960)
    const float* W2 = (const float*)d_in[3];  // (512, 1960)
    const float* b2 = (const float*)d_in[4];  // (512)
    float* out = (float*)d_out;               // (11520, 512)

    float *hptr, *fptr;
    __nv_bfloat16 *xh, *xl, *w1h, *w1l, *w2h, *w2l, *gh, *gl;
    cudaGetSymbolAddress((void**)&hptr, g_h);
    cudaGetSymbolAddress((void**)&fptr, g_fold);
    cudaGetSymbolAddress((void**)&xh,  g_xh);
    cudaGetSymbolAddress((void**)&xl,  g_xl);
    cudaGetSymbolAddress((void**)&w1h, g_w1h);
    cudaGetSymbolAddress((void**)&w1l, g_w1l);
    cudaGetSymbolAddress((void**)&w2h, g_w2h);
    cudaGetSymbolAddress((void**)&w2l, g_w2l);
    cudaGetSymbolAddress((void**)&gh,  g_gh);
    cudaGetSymbolAddress((void**)&gl,  g_gl);

    static bool attr_set = false;
    if (!attr_set) {
        cudaFuncSetAttribute(gemm_bf16x3_nt_bias,
                             cudaFuncAttributeMaxDynamicSharedMemorySize,
                             GEMM_SMEM);
        attr_set = true;
    }

    // Split conversions (all sizes are multiples of 4)
    {
        int n4 = NROWS * DIMD / 4;
        split_bf16_kernel<<<(n4 + 255) / 256, 256>>>(x, xh, xl, n4);
        n4 = HID * DIMD / 4;
        split_bf16_kernel<<<(n4 + 255) / 256, 256>>>(W1, w1h, w1l, n4);
        n4 = DIMD * HID / 4;
        split_bf16_kernel<<<(n4 + 255) / 256, 256>>>(W2, w2h, w2l, n4);
    }

    // GEMM1: h = x @ W1^T + b1   (M=11520, N=1960, K=512)
    {
        dim3 grid((HID + BN - 1) / BN, NROWS / BM);
        gemm_bf16x3_nt_bias<<<grid, 256, GEMM_SMEM>>>(
            NROWS, HID, DIMD, xh, xl, w1h, w1l, b1, hptr);
    }

    // Fold (gather)
    {
        const int total = BPRIME * NCH * NPIX;
        fold_kernel<<<(total + 255) / 256, 256>>>(hptr, fptr);
    }

    // Unfold + norm + gelu -> bf16 hi/lo
    {
        const int total = NROWS * HID;
        unfold_gelu_kernel<<<(total + 255) / 256, 256>>>(fptr, gh, gl);
    }

    // GEMM2: out = gelu(y) @ W2^T + b2  (M=11520, N=512, K=1960)
    {
        dim3 grid((DIMD + BN - 1) / BN, NROWS / BM);
        gemm_bf16x3_nt_bias<<<grid, 256, GEMM_SMEM>>>(
            NROWS, DIMD, HID, gh, gl, w2h, w2l, b2, out);
    }
}